// round 16
// baseline (speedup 1.0000x reference)
#include <cuda_runtime.h>
#include <cuda_bf16.h>
#include <cuda_fp16.h>
#include <cstdint>

#define NN 50000
#define EE 800000
#define FDIM 256
#define HEADS 4
#define HID 64
#define BNPART 256
#define MTILES 391                     // (NN+127)/128
#define HISTROWS 782                   // ceil(EE/(4*256))

// ---------------- scratch (static device globals; allocation-free) ----------------
__device__ float  d_y1[NN * FDIM];     // linear1 output + GAT1 aggregation -> x1 (relu'd by gat1)
__device__ __half d_h1h[NN * FDIM];    // GAT1 transformed features (fp16)
__device__ __nv_bfloat16 d_a_hi[NN * FDIM];
__device__ __nv_bfloat16 d_a_lo[NN * FDIM];
__device__ __nv_bfloat16 d_w_hi[2 * FDIM * FDIM];
__device__ __nv_bfloat16 d_w_lo[2 * FDIM * FDIM];
__device__ float4 d_als1[NN];
__device__ float4 d_ald1[NN];
__device__ float4 d_p3[NN];            // packed layer-2: (als3, h0, h1, ald3)
__device__ float  d_bnps[BNPART * FDIM];
__device__ float  d_bnpq[BNPART * FDIM];
__device__ float  d_bnsum2[FDIM];      // BN3 sums (atomic, filled by gat1_warp)
__device__ float  d_bnsq2[FDIM];
__device__ float  d_scale[FDIM];
__device__ float  d_shift[FDIM];
__device__ int d_rowptr[NN + 1];
__device__ int d_cursor[NN];
__device__ int d_csr_src[EE];
__device__ int d_chunksum[64];

__device__ __forceinline__ float lrelu(float x) { return x > 0.f ? x : 0.2f * x; }

// ---------------- BN1 stats: per-block partials (no atomics, no pre-zero) ----------------
__global__ void bn_stats(const float* __restrict__ x) {
    int c = threadIdx.x;
    float s = 0.f, s2 = 0.f;
    for (int r = blockIdx.x; r < NN; r += BNPART) {
        float v = x[r * FDIM + c];
        s += v; s2 += v * v;
    }
    d_bnps[blockIdx.x * FDIM + c] = s;
    d_bnpq[blockIdx.x * FDIM + c] = s2;
}
__global__ void bn_finalize(const float* __restrict__ g, const float* __restrict__ b) {
    int c = threadIdx.x;
    float s = 0.f, q = 0.f;
    #pragma unroll 8
    for (int i = 0; i < BNPART; i++) {
        s += d_bnps[i * FDIM + c];
        q += d_bnpq[i * FDIM + c];
    }
    const float invn = 1.0f / (float)NN;
    float mu = s * invn;
    float var = q * invn - mu * mu;
    float rs = rsqrtf(var + 1e-5f);
    float sc = rs * g[c];
    d_scale[c] = sc;
    d_shift[c] = b[c] - mu * sc;
}
// BN3 finalize: reads atomic accumulators filled by gat1_warp
__global__ void bn_finalize2(const float* __restrict__ g, const float* __restrict__ b) {
    int c = threadIdx.x;
    const float invn = 1.0f / (float)NN;
    float mu = d_bnsum2[c] * invn;
    float var = d_bnsq2[c] * invn - mu * mu;
    float rs = rsqrtf(var + 1e-5f);
    float sc = rs * g[c];
    d_scale[c] = sc;
    d_shift[c] = b[c] - mu * sc;
}

// ---------------- prep: BN+hi/lo conv of A, weight conv, rowptr zero, BN3-acc zero ----------------
#define PREP_A 12500
#define PREP_W 512
#define PREP_Z 197                     // 196 rowptr blocks + 1 bnsum2/bnsq2 block
__global__ void prep_k(const float* __restrict__ x,
                       const float* __restrict__ W0, const float* __restrict__ W1) {
    int bid = blockIdx.x;
    int t = threadIdx.x;
    if (bid < PREP_A) {
        int i = bid * 256 + t;
        int c = (i & 63) << 2;
        float4 v = ((const float4*)x)[i];
        float4 sc = *(const float4*)&d_scale[c];
        float4 sh = *(const float4*)&d_shift[c];
        float a0 = v.x * sc.x + sh.x, a1 = v.y * sc.y + sh.y;
        float a2 = v.z * sc.z + sh.z, a3 = v.w * sc.w + sh.w;
        __nv_bfloat16 h0 = __float2bfloat16_rn(a0), h1 = __float2bfloat16_rn(a1);
        __nv_bfloat16 h2 = __float2bfloat16_rn(a2), h3 = __float2bfloat16_rn(a3);
        __nv_bfloat162* ph = (__nv_bfloat162*)d_a_hi;
        ph[i * 2]     = __nv_bfloat162(h0, h1);
        ph[i * 2 + 1] = __nv_bfloat162(h2, h3);
        __nv_bfloat162* pl = (__nv_bfloat162*)d_a_lo;
        pl[i * 2]     = __nv_bfloat162(__float2bfloat16_rn(a0 - __bfloat162float(h0)),
                                       __float2bfloat16_rn(a1 - __bfloat162float(h1)));
        pl[i * 2 + 1] = __nv_bfloat162(__float2bfloat16_rn(a2 - __bfloat162float(h2)),
                                       __float2bfloat16_rn(a3 - __bfloat162float(h3)));
    } else if (bid < PREP_A + PREP_W) {
        int i = (bid - PREP_A) * 256 + t;
        int mat = i >> 16, r = i & 65535;
        int n = r >> 8, k = r & 255;
        const float* W = mat ? W1 : W0;
        float v = W[k * 256 + n];
        __nv_bfloat16 h = __float2bfloat16_rn(v);
        d_w_hi[i] = h;
        d_w_lo[i] = __float2bfloat16_rn(v - __bfloat162float(h));
    } else if (bid < PREP_A + PREP_W + 196) {
        int i = (bid - PREP_A - PREP_W) * 256 + t;
        if (i <= NN) d_rowptr[i] = 0;
    } else {
        d_bnsum2[t] = 0.f;
        d_bnsq2[t] = 0.f;
    }
}

// ---------------- CSR scan (scan2 folded into scan3) ----------------
__global__ void scan1_k() {
    __shared__ int s[1024];
    int tid = threadIdx.x;
    int i = blockIdx.x * 1024 + tid;
    int v = (i <= NN) ? d_rowptr[i] : 0;
    s[tid] = v;
    __syncthreads();
    #pragma unroll
    for (int off = 1; off < 1024; off <<= 1) {
        int add = (tid >= off) ? s[tid - off] : 0;
        __syncthreads();
        s[tid] += add;
        __syncthreads();
    }
    if (i <= NN) {
        d_rowptr[i] = s[tid];
        if (blockIdx.x == 0 && i < NN) d_cursor[i] = s[tid];
    }
    if (tid == 1023) d_chunksum[blockIdx.x] = s[1023];
}
__global__ void scan3_k() {
    int chunk = blockIdx.x + 1;
    int base = 0;
    for (int j = 0; j < chunk; j++) base += d_chunksum[j];
    int i = chunk * 1024 + threadIdx.x;
    if (i <= NN) {
        int v = d_rowptr[i] + base;
        d_rowptr[i] = v;
        if (i < NN) d_cursor[i] = v;
    }
}

// ---------------- fused: CSR scatter + layer-1 logit contributions (fp16 h1) ----------------
#define SCAT_B 3125
#define AL_B 6250
__global__ void scatter_al_k(const int* __restrict__ ei,
                             const float* __restrict__ asrc,
                             const float* __restrict__ adst) {
    if (blockIdx.x < SCAT_B) {
        int e = blockIdx.x * 256 + threadIdx.x;
        if (e >= EE) return;
        int s = ei[e], t = ei[EE + e];
        int pos = atomicAdd(&d_cursor[t], 1);
        d_csr_src[pos] = s;
        return;
    }
    int warp = ((blockIdx.x - SCAT_B) * 256 + threadIdx.x) >> 5;
    int lane = threadIdx.x & 31;
    if (warp >= NN) return;
    int head = lane >> 3;
    int coff = lane * 8;
    uint4 raw = *(const uint4*)&d_h1h[(size_t)warp * 256 + coff];
    __half2 p0 = *(__half2*)&raw.x, p1 = *(__half2*)&raw.y;
    __half2 p2 = *(__half2*)&raw.z, p3 = *(__half2*)&raw.w;
    float2 f0 = __half22float2(p0), f1 = __half22float2(p1);
    float2 f2 = __half22float2(p2), f3 = __half22float2(p3);
    int cbase = coff & 63;
    const float* as = asrc + head * 64 + cbase;
    const float* ad = adst + head * 64 + cbase;
    float s = f0.x*as[0] + f0.y*as[1] + f1.x*as[2] + f1.y*as[3]
            + f2.x*as[4] + f2.y*as[5] + f3.x*as[6] + f3.y*as[7];
    float d = f0.x*ad[0] + f0.y*ad[1] + f1.x*ad[2] + f1.y*ad[3]
            + f2.x*ad[4] + f2.y*ad[5] + f3.x*ad[6] + f3.y*ad[7];
    #pragma unroll
    for (int off = 4; off > 0; off >>= 1) {
        s += __shfl_down_sync(0xffffffff, s, off);
        d += __shfl_down_sync(0xffffffff, d, off);
    }
    if ((lane & 7) == 0) {
        ((float*)&d_als1[warp])[head] = s;
        ((float*)&d_ald1[warp])[head] = d;
    }
}

// ---------------- bf16 split tensor-core GEMM (+ edge histogram tail blocks) ----------------
#define SLDA 24
#define PLANE (128 * SLDA * 2)
#define STG (4 * PLANE)
#define GSMEM (4 * STG)

__device__ __forceinline__ void mma16816(float* d, const uint32_t* a, uint32_t b0, uint32_t b1) {
    asm volatile("mma.sync.aligned.m16n8k16.row.col.f32.bf16.bf16.f32 "
                 "{%0,%1,%2,%3}, {%4,%5,%6,%7}, {%8,%9}, {%0,%1,%2,%3};"
                 : "+f"(d[0]), "+f"(d[1]), "+f"(d[2]), "+f"(d[3])
                 : "r"(a[0]), "r"(a[1]), "r"(a[2]), "r"(a[3]), "r"(b0), "r"(b1));
}
__device__ __forceinline__ void ldsm4(uint32_t* r, uint32_t addr) {
    asm volatile("ldmatrix.sync.aligned.m8n8.x4.shared.b16 {%0,%1,%2,%3}, [%4];"
                 : "=r"(r[0]), "=r"(r[1]), "=r"(r[2]), "=r"(r[3]) : "r"(addr));
}
__device__ __forceinline__ void cpa16(uint32_t saddr, const void* gaddr, int bytes) {
    asm volatile("cp.async.cg.shared.global [%0], [%1], 16, %2;"
                 :: "r"(saddr), "l"(gaddr), "r"(bytes));
}

extern __shared__ char dynsmem[];

__global__ void __launch_bounds__(256, 2)
gemm_bf16(const float* __restrict__ b0a, const float* __restrict__ b0b,
          const int* __restrict__ ei) {
    int t = threadIdx.x;

    if (blockIdx.y >= MTILES) {
        int idx = (blockIdx.y - MTILES) * 4 + blockIdx.x;
        int e = idx * 256 + t;
        if (e < EE) atomicAdd(&d_rowptr[ei[EE + e] + 1], 1);
        return;
    }

    int mat = blockIdx.x >> 1;
    int n0 = (blockIdx.x & 1) * 128;
    int m0 = blockIdx.y * 128;
    const __nv_bfloat16* Bh = d_w_hi + mat * 65536;
    const __nv_bfloat16* Bl = d_w_lo + mat * 65536;

    int lrow = t >> 1, seg = t & 1;
    int gm = m0 + lrow;
    bool aok = gm < NN;
    int gmc = aok ? gm : 0;
    int abytes = aok ? 16 : 0;

    const char* gAh = (const char*)(d_a_hi + (size_t)gmc * 256) + seg * 16;
    const char* gAl = (const char*)(d_a_lo + (size_t)gmc * 256) + seg * 16;
    const char* gBh = (const char*)(Bh + (size_t)(n0 + lrow) * 256) + seg * 16;
    const char* gBl = (const char*)(Bl + (size_t)(n0 + lrow) * 256) + seg * 16;

    uint32_t smem0 = (uint32_t)__cvta_generic_to_shared(dynsmem);
    uint32_t rowoff = (uint32_t)(lrow * 48 + seg * 16);

    auto issue = [&](int slab, int buf) {
        uint32_t base = smem0 + buf * STG + rowoff;
        int go = slab * 32;
        cpa16(base,             gAh + go, abytes);
        cpa16(base + PLANE,     gAl + go, abytes);
        cpa16(base + 2 * PLANE, gBh + go, 16);
        cpa16(base + 3 * PLANE, gBl + go, 16);
        asm volatile("cp.async.commit_group;");
    };

    issue(0, 0);
    issue(1, 1);
    issue(2, 2);

    int wid = t >> 5, lane = t & 31;
    int wm0 = (wid & 1) * 64, wn0 = (wid >> 1) * 32;
    float acc[4][4][4] = {};

    int a_r = (lane & 15);
    int a_c = (lane >> 4) << 3;
    int b_r = (lane & 7) + ((lane & 16) ? 8 : 0);
    int b_c = (lane & 8) ? 8 : 0;

    for (int s = 0; s < 16; s++) {
        asm volatile("cp.async.wait_group 2;");
        __syncthreads();
        if (s + 3 < 16) issue(s + 3, (s + 3) & 3);
        else            asm volatile("cp.async.commit_group;");

        uint32_t sAu = smem0 + (s & 3) * STG;
        uint32_t sBu = sAu + 2 * PLANE;
        uint32_t bh[2][4], bl[2][4];
        #pragma unroll
        for (int jp = 0; jp < 2; jp++) {
            uint32_t addr = sBu + (uint32_t)(((wn0 + jp * 16 + b_r) * SLDA + b_c) * 2);
            ldsm4(bh[jp], addr);
            ldsm4(bl[jp], addr + PLANE);
        }
        #pragma unroll
        for (int i = 0; i < 4; i++) {
            uint32_t ah[4], al[4];
            uint32_t addr = sAu + (uint32_t)(((wm0 + i * 16 + a_r) * SLDA + a_c) * 2);
            ldsm4(ah, addr);
            ldsm4(al, addr + PLANE);
            #pragma unroll
            for (int j = 0; j < 4; j++) {
                int jp = j >> 1, o = (j & 1) * 2;
                mma16816(acc[i][j], ah, bh[jp][o], bh[jp][o + 1]);
                mma16816(acc[i][j], ah, bl[jp][o], bl[jp][o + 1]);
                mma16816(acc[i][j], al, bh[jp][o], bh[jp][o + 1]);
            }
        }
    }

    int g = lane >> 2, tq = lane & 3;
    if (!mat) {
        float* C = (float*)d_y1;
        #pragma unroll
        for (int j = 0; j < 4; j++) {
            int gcol = n0 + wn0 + j * 8 + tq * 2;
            float bx = b0a[gcol] + b0b[gcol];
            float by = b0a[gcol + 1] + b0b[gcol + 1];
            #pragma unroll
            for (int i = 0; i < 4; i++) {
                int r0 = m0 + wm0 + i * 16 + g;
                if (r0 < NN)
                    *(float2*)&C[(size_t)r0 * 256 + gcol] =
                        make_float2(acc[i][j][0] + bx, acc[i][j][1] + by);
                int r1 = r0 + 8;
                if (r1 < NN)
                    *(float2*)&C[(size_t)r1 * 256 + gcol] =
                        make_float2(acc[i][j][2] + bx, acc[i][j][3] + by);
            }
        }
    } else {
        __half* C = (__half*)d_h1h;
        #pragma unroll
        for (int j = 0; j < 4; j++) {
            int gcol = n0 + wn0 + j * 8 + tq * 2;
            #pragma unroll
            for (int i = 0; i < 4; i++) {
                int r0 = m0 + wm0 + i * 16 + g;
                if (r0 < NN)
                    *(__half2*)&C[(size_t)r0 * 256 + gcol] =
                        __floats2half2_rn(acc[i][j][0], acc[i][j][1]);
                int r1 = r0 + 8;
                if (r1 < NN)
                    *(__half2*)&C[(size_t)r1 * 256 + gcol] =
                        __floats2half2_rn(acc[i][j][2], acc[i][j][3]);
            }
        }
    }
}

// ---------------- layer-1 GAT + ReLU + fused BN3 stats ----------------
// warp/dst; final x1 row is in registers at epilogue -> relu + per-channel
// sum/sumsq accumulated in block smem, one global atomicAdd per channel/block.
__global__ void gat1_warp() {
    __shared__ float s_sum[256], s_sq[256];
    int t = threadIdx.x;
    s_sum[t] = 0.f; s_sq[t] = 0.f;
    __syncthreads();

    int d = (blockIdx.x * blockDim.x + t) >> 5;
    int lane = t & 31;
    int coff = lane * 8;

    if (d < NN) {
        int b = d_rowptr[d], e = d_rowptr[d + 1];
        float4* yp = (float4*)&d_y1[(size_t)d * 256 + coff];
        float4 o0 = yp[0], o1 = yp[1];

        if (b != e) {
            float4 ald = d_ald1[d];
            int h = lane >> 3;
            float4 acc0 = make_float4(0.f, 0.f, 0.f, 0.f);
            float4 acc1 = make_float4(0.f, 0.f, 0.f, 0.f);
            float den = 0.f;
            const __half* __restrict__ hp = (const __half*)d_h1h;
            for (int c0 = b; c0 < e; c0 += 32) {
                int cnt = min(32, e - c0);
                int src = 0;
                float4 ex = make_float4(0.f, 0.f, 0.f, 0.f);
                if (lane < cnt) {
                    src = d_csr_src[c0 + lane];
                    float4 a = d_als1[src];
                    ex.x = __expf(lrelu(a.x + ald.x));
                    ex.y = __expf(lrelu(a.y + ald.y));
                    ex.z = __expf(lrelu(a.z + ald.z));
                    ex.w = __expf(lrelu(a.w + ald.w));
                }
                #pragma unroll 4
                for (int j = 0; j < cnt; j++) {
                    int   sj = __shfl_sync(0xffffffffu, src,  j);
                    float e0 = __shfl_sync(0xffffffffu, ex.x, j);
                    float e1 = __shfl_sync(0xffffffffu, ex.y, j);
                    float e2 = __shfl_sync(0xffffffffu, ex.z, j);
                    float e3 = __shfl_sync(0xffffffffu, ex.w, j);
                    float w = (h == 0) ? e0 : (h == 1) ? e1 : (h == 2) ? e2 : e3;
                    den += w;
                    uint4 raw = *(const uint4*)&hp[(size_t)sj * 256 + coff];
                    float2 f0 = __half22float2(*(__half2*)&raw.x);
                    float2 f1 = __half22float2(*(__half2*)&raw.y);
                    float2 f2 = __half22float2(*(__half2*)&raw.z);
                    float2 f3 = __half22float2(*(__half2*)&raw.w);
                    acc0.x += w * f0.x; acc0.y += w * f0.y;
                    acc0.z += w * f1.x; acc0.w += w * f1.y;
                    acc1.x += w * f2.x; acc1.y += w * f2.y;
                    acc1.z += w * f3.x; acc1.w += w * f3.y;
                }
            }
            float r = 1.f / (den + 1e-16f);
            o0.x += acc0.x * r; o0.y += acc0.y * r; o0.z += acc0.z * r; o0.w += acc0.w * r;
            o1.x += acc1.x * r; o1.y += acc1.y * r; o1.z += acc1.z * r; o1.w += acc1.w * r;
        }
        // ReLU (applies to isolated nodes too — their GAT message is 0)
        o0.x = fmaxf(o0.x, 0.f); o0.y = fmaxf(o0.y, 0.f);
        o0.z = fmaxf(o0.z, 0.f); o0.w = fmaxf(o0.w, 0.f);
        o1.x = fmaxf(o1.x, 0.f); o1.y = fmaxf(o1.y, 0.f);
        o1.z = fmaxf(o1.z, 0.f); o1.w = fmaxf(o1.w, 0.f);
        yp[0] = o0; yp[1] = o1;
        // BN3 stats contribution (per-channel into block smem)
        float v[8] = {o0.x, o0.y, o0.z, o0.w, o1.x, o1.y, o1.z, o1.w};
        #pragma unroll
        for (int q = 0; q < 8; q++) {
            atomicAdd(&s_sum[coff + q], v[q]);
            atomicAdd(&s_sq[coff + q], v[q] * v[q]);
        }
    }
    __syncthreads();
    atomicAdd(&d_bnsum2[t], s_sum[t]);
    atomicAdd(&d_bnsq2[t], s_sq[t]);
}

// ---------------- layer 2: BN (x1 already relu'd) + linear3 + GAT2 features/logits ----------------
__global__ void layer2_row(const float* __restrict__ lin3W, const float* __restrict__ lin3b,
                           const float* __restrict__ con3W, const float* __restrict__ asrc,
                           const float* __restrict__ adst, const float* __restrict__ con3b,
                           float* __restrict__ out) {
    int warp = (blockIdx.x * blockDim.x + threadIdx.x) >> 5;
    int lane = threadIdx.x & 31;
    if (warp >= NN) return;
    const float* row = (const float*)d_y1 + (size_t)warp * 256;
    float y0 = 0.f, y1v = 0.f, h0 = 0.f, h1v = 0.f;
    #pragma unroll
    for (int q = 0; q < 8; q++) {
        int c = lane + q * 32;
        float v = row[c] * d_scale[c] + d_shift[c];
        y0  += v * lin3W[c * 2];
        y1v += v * lin3W[c * 2 + 1];
        h0  += v * con3W[c * 2];
        h1v += v * con3W[c * 2 + 1];
    }
    #pragma unroll
    for (int off = 16; off > 0; off >>= 1) {
        y0  += __shfl_xor_sync(0xffffffff, y0,  off);
        y1v += __shfl_xor_sync(0xffffffff, y1v, off);
        h0  += __shfl_xor_sync(0xffffffff, h0,  off);
        h1v += __shfl_xor_sync(0xffffffff, h1v, off);
    }
    if (lane == 0) {
        out[warp * 2]     = y0  + lin3b[0] + con3b[0];
        out[warp * 2 + 1] = y1v + lin3b[1] + con3b[1];
        d_p3[warp] = make_float4(h0 * asrc[0] + h1v * asrc[1],
                                 h0, h1v,
                                 h0 * adst[0] + h1v * adst[1]);
    }
}

// ---------------- layer-2 GAT + final relu (warp/dst, single LDG.128 per edge) ----------------
__global__ void gat_l2(float* __restrict__ out) {
    int d = (blockIdx.x * blockDim.x + threadIdx.x) >> 5;
    int lane = threadIdx.x & 31;
    if (d >= NN) return;
    int b = d_rowptr[d], e = d_rowptr[d + 1];
    float ald = d_p3[d].w;
    float den = 0.f, m0 = 0.f, m1 = 0.f;
    for (int j = b + lane; j < e; j += 32) {
        int src = d_csr_src[j];
        float4 p = d_p3[src];
        float ex = __expf(lrelu(p.x + ald));
        den += ex; m0 += ex * p.y; m1 += ex * p.z;
    }
    #pragma unroll
    for (int off = 16; off > 0; off >>= 1) {
        den += __shfl_xor_sync(0xffffffff, den, off);
        m0  += __shfl_xor_sync(0xffffffff, m0,  off);
        m1  += __shfl_xor_sync(0xffffffff, m1,  off);
    }
    if (lane == 0) {
        float r = 1.f / (den + 1e-16f);
        out[d * 2]     = fmaxf(out[d * 2]     + m0 * r, 0.f);
        out[d * 2 + 1] = fmaxf(out[d * 2 + 1] + m1 * r, 0.f);
    }
}

// ---------------- launch ----------------
extern "C" void kernel_launch(void* const* d_in, const int* in_sizes, int n_in,
                              void* d_out, int out_size) {
    const float* x         = (const float*)d_in[0];
    const int*   ei        = (const int*)d_in[1];
    const float* bn1_g     = (const float*)d_in[2];
    const float* bn1_b     = (const float*)d_in[3];
    const float* lin1_W    = (const float*)d_in[4];
    const float* lin1_b    = (const float*)d_in[5];
    const float* con1_W    = (const float*)d_in[6];
    const float* con1_asrc = (const float*)d_in[7];
    const float* con1_adst = (const float*)d_in[8];
    const float* con1_b    = (const float*)d_in[9];
    const float* bn3_g     = (const float*)d_in[10];
    const float* bn3_b     = (const float*)d_in[11];
    const float* lin3_W    = (const float*)d_in[12];
    const float* lin3_b    = (const float*)d_in[13];
    const float* con3_W    = (const float*)d_in[14];
    const float* con3_asrc = (const float*)d_in[15];
    const float* con3_adst = (const float*)d_in[16];
    const float* con3_b    = (const float*)d_in[17];
    float* out = (float*)d_out;

    const int NCHUNK = (NN + 1 + 1023) / 1024;   // 49

    cudaFuncSetAttribute(gemm_bf16, cudaFuncAttributeMaxDynamicSharedMemorySize, GSMEM);

    // 1-3: BN1 stats/finalize, fused prep (bnconv + wtconv + rowptr/BN3-acc zero)
    bn_stats<<<BNPART, 256>>>(x);
    bn_finalize<<<1, 256>>>(bn1_g, bn1_b);
    prep_k<<<PREP_A + PREP_W + PREP_Z, 256>>>(x, lin1_W, con1_W);

    // 4 (ncu-profiled slot): dual GEMM + histogram tail blocks
    gemm_bf16<<<dim3(4, MTILES + HISTROWS), 256, GSMEM>>>(lin1_b, con1_b, ei);

    // 5-6: CSR scan, cursor init fused
    scan1_k<<<NCHUNK, 1024>>>();
    scan3_k<<<NCHUNK - 1, 1024>>>();

    // 7: fused scatter + layer-1 logit contributions
    scatter_al_k<<<SCAT_B + AL_B, 256>>>(ei, con1_asrc, con1_adst);

    // 8: GAT1 softmax+aggregate + ReLU + fused BN3 stats
    gat1_warp<<<(NN + 7) / 8, 256>>>();

    // 9: BN3 finalize (reads atomic accumulators)
    bn_finalize2<<<1, 256>>>(bn3_g, bn3_b);

    // 10-11: layer 2
    layer2_row<<<(NN + 7) / 8, 256>>>(lin3_W, lin3_b, con3_W, con3_asrc, con3_adst, con3_b, out);
    gat_l2<<<(NN + 7) / 8, 256>>>(out);
}

// round 17
// speedup vs baseline: 1.1484x; 1.1484x over previous
#include <cuda_runtime.h>
#include <cuda_bf16.h>
#include <cuda_fp16.h>
#include <cstdint>

#define NN 50000
#define EE 800000
#define FDIM 256
#define HEADS 4
#define HID 64
#define BNPART 256
#define MTILES 391                     // (NN+127)/128
#define HISTROWS 782                   // ceil(EE/(4*256))

// ---------------- scratch (static device globals; allocation-free) ----------------
__device__ float  d_y1[NN * FDIM];     // linear1 output + GAT1 aggregation -> x1 (relu'd by gat1)
__device__ __half d_h1h[NN * FDIM];    // GAT1 transformed features (fp16)
__device__ __nv_bfloat16 d_a_hi[NN * FDIM];
__device__ __nv_bfloat16 d_a_lo[NN * FDIM];
__device__ __nv_bfloat16 d_w_hi[2 * FDIM * FDIM];
__device__ __nv_bfloat16 d_w_lo[2 * FDIM * FDIM];
__device__ float4 d_als1[NN];
__device__ float4 d_ald1[NN];
__device__ float4 d_p3[NN];            // packed layer-2: (als3, h0, h1, ald3)
__device__ float  d_bnps[BNPART * FDIM];
__device__ float  d_bnpq[BNPART * FDIM];
__device__ float  d_bnsum2[FDIM];      // BN3 sums (one global atomic per block/channel)
__device__ float  d_bnsq2[FDIM];
__device__ float  d_scale[FDIM];
__device__ float  d_shift[FDIM];
__device__ int d_rowptr[NN + 1];
__device__ int d_cursor[NN];
__device__ int d_csr_src[EE];
__device__ int d_chunksum[64];

__device__ __forceinline__ float lrelu(float x) { return x > 0.f ? x : 0.2f * x; }

// ---------------- BN1 stats: per-block partials (no atomics, no pre-zero) ----------------
__global__ void bn_stats(const float* __restrict__ x) {
    int c = threadIdx.x;
    float s = 0.f, s2 = 0.f;
    for (int r = blockIdx.x; r < NN; r += BNPART) {
        float v = x[r * FDIM + c];
        s += v; s2 += v * v;
    }
    d_bnps[blockIdx.x * FDIM + c] = s;
    d_bnpq[blockIdx.x * FDIM + c] = s2;
}
__global__ void bn_finalize(const float* __restrict__ g, const float* __restrict__ b) {
    int c = threadIdx.x;
    float s = 0.f, q = 0.f;
    #pragma unroll 8
    for (int i = 0; i < BNPART; i++) {
        s += d_bnps[i * FDIM + c];
        q += d_bnpq[i * FDIM + c];
    }
    const float invn = 1.0f / (float)NN;
    float mu = s * invn;
    float var = q * invn - mu * mu;
    float rs = rsqrtf(var + 1e-5f);
    float sc = rs * g[c];
    d_scale[c] = sc;
    d_shift[c] = b[c] - mu * sc;
}
// BN3 finalize: reads atomic accumulators filled by gat1_warp
__global__ void bn_finalize2(const float* __restrict__ g, const float* __restrict__ b) {
    int c = threadIdx.x;
    const float invn = 1.0f / (float)NN;
    float mu = d_bnsum2[c] * invn;
    float var = d_bnsq2[c] * invn - mu * mu;
    float rs = rsqrtf(var + 1e-5f);
    float sc = rs * g[c];
    d_scale[c] = sc;
    d_shift[c] = b[c] - mu * sc;
}

// ---------------- prep: BN+hi/lo conv of A, weight conv, rowptr zero, BN3-acc zero ----------------
#define PREP_A 12500
#define PREP_W 512
#define PREP_Z 197                     // 196 rowptr blocks + 1 bnsum2/bnsq2 block
__global__ void prep_k(const float* __restrict__ x,
                       const float* __restrict__ W0, const float* __restrict__ W1) {
    int bid = blockIdx.x;
    int t = threadIdx.x;
    if (bid < PREP_A) {
        int i = bid * 256 + t;
        int c = (i & 63) << 2;
        float4 v = ((const float4*)x)[i];
        float4 sc = *(const float4*)&d_scale[c];
        float4 sh = *(const float4*)&d_shift[c];
        float a0 = v.x * sc.x + sh.x, a1 = v.y * sc.y + sh.y;
        float a2 = v.z * sc.z + sh.z, a3 = v.w * sc.w + sh.w;
        __nv_bfloat16 h0 = __float2bfloat16_rn(a0), h1 = __float2bfloat16_rn(a1);
        __nv_bfloat16 h2 = __float2bfloat16_rn(a2), h3 = __float2bfloat16_rn(a3);
        __nv_bfloat162* ph = (__nv_bfloat162*)d_a_hi;
        ph[i * 2]     = __nv_bfloat162(h0, h1);
        ph[i * 2 + 1] = __nv_bfloat162(h2, h3);
        __nv_bfloat162* pl = (__nv_bfloat162*)d_a_lo;
        pl[i * 2]     = __nv_bfloat162(__float2bfloat16_rn(a0 - __bfloat162float(h0)),
                                       __float2bfloat16_rn(a1 - __bfloat162float(h1)));
        pl[i * 2 + 1] = __nv_bfloat162(__float2bfloat16_rn(a2 - __bfloat162float(h2)),
                                       __float2bfloat16_rn(a3 - __bfloat162float(h3)));
    } else if (bid < PREP_A + PREP_W) {
        int i = (bid - PREP_A) * 256 + t;
        int mat = i >> 16, r = i & 65535;
        int n = r >> 8, k = r & 255;
        const float* W = mat ? W1 : W0;
        float v = W[k * 256 + n];
        __nv_bfloat16 h = __float2bfloat16_rn(v);
        d_w_hi[i] = h;
        d_w_lo[i] = __float2bfloat16_rn(v - __bfloat162float(h));
    } else if (bid < PREP_A + PREP_W + 196) {
        int i = (bid - PREP_A - PREP_W) * 256 + t;
        if (i <= NN) d_rowptr[i] = 0;
    } else {
        d_bnsum2[t] = 0.f;
        d_bnsq2[t] = 0.f;
    }
}

// ---------------- CSR scan (scan2 folded into scan3) ----------------
__global__ void scan1_k() {
    __shared__ int s[1024];
    int tid = threadIdx.x;
    int i = blockIdx.x * 1024 + tid;
    int v = (i <= NN) ? d_rowptr[i] : 0;
    s[tid] = v;
    __syncthreads();
    #pragma unroll
    for (int off = 1; off < 1024; off <<= 1) {
        int add = (tid >= off) ? s[tid - off] : 0;
        __syncthreads();
        s[tid] += add;
        __syncthreads();
    }
    if (i <= NN) {
        d_rowptr[i] = s[tid];
        if (blockIdx.x == 0 && i < NN) d_cursor[i] = s[tid];
    }
    if (tid == 1023) d_chunksum[blockIdx.x] = s[1023];
}
__global__ void scan3_k() {
    int chunk = blockIdx.x + 1;
    int base = 0;
    for (int j = 0; j < chunk; j++) base += d_chunksum[j];
    int i = chunk * 1024 + threadIdx.x;
    if (i <= NN) {
        int v = d_rowptr[i] + base;
        d_rowptr[i] = v;
        if (i < NN) d_cursor[i] = v;
    }
}

// ---------------- fused: CSR scatter + layer-1 logit contributions (fp16 h1) ----------------
#define SCAT_B 3125
#define AL_B 6250
__global__ void scatter_al_k(const int* __restrict__ ei,
                             const float* __restrict__ asrc,
                             const float* __restrict__ adst) {
    if (blockIdx.x < SCAT_B) {
        int e = blockIdx.x * 256 + threadIdx.x;
        if (e >= EE) return;
        int s = ei[e], t = ei[EE + e];
        int pos = atomicAdd(&d_cursor[t], 1);
        d_csr_src[pos] = s;
        return;
    }
    int warp = ((blockIdx.x - SCAT_B) * 256 + threadIdx.x) >> 5;
    int lane = threadIdx.x & 31;
    if (warp >= NN) return;
    int head = lane >> 3;
    int coff = lane * 8;
    uint4 raw = *(const uint4*)&d_h1h[(size_t)warp * 256 + coff];
    __half2 p0 = *(__half2*)&raw.x, p1 = *(__half2*)&raw.y;
    __half2 p2 = *(__half2*)&raw.z, p3 = *(__half2*)&raw.w;
    float2 f0 = __half22float2(p0), f1 = __half22float2(p1);
    float2 f2 = __half22float2(p2), f3 = __half22float2(p3);
    int cbase = coff & 63;
    const float* as = asrc + head * 64 + cbase;
    const float* ad = adst + head * 64 + cbase;
    float s = f0.x*as[0] + f0.y*as[1] + f1.x*as[2] + f1.y*as[3]
            + f2.x*as[4] + f2.y*as[5] + f3.x*as[6] + f3.y*as[7];
    float d = f0.x*ad[0] + f0.y*ad[1] + f1.x*ad[2] + f1.y*ad[3]
            + f2.x*ad[4] + f2.y*ad[5] + f3.x*ad[6] + f3.y*ad[7];
    #pragma unroll
    for (int off = 4; off > 0; off >>= 1) {
        s += __shfl_down_sync(0xffffffff, s, off);
        d += __shfl_down_sync(0xffffffff, d, off);
    }
    if ((lane & 7) == 0) {
        ((float*)&d_als1[warp])[head] = s;
        ((float*)&d_ald1[warp])[head] = d;
    }
}

// ---------------- bf16 split tensor-core GEMM (+ edge histogram tail blocks) ----------------
#define SLDA 24
#define PLANE (128 * SLDA * 2)
#define STG (4 * PLANE)
#define GSMEM (4 * STG)

__device__ __forceinline__ void mma16816(float* d, const uint32_t* a, uint32_t b0, uint32_t b1) {
    asm volatile("mma.sync.aligned.m16n8k16.row.col.f32.bf16.bf16.f32 "
                 "{%0,%1,%2,%3}, {%4,%5,%6,%7}, {%8,%9}, {%0,%1,%2,%3};"
                 : "+f"(d[0]), "+f"(d[1]), "+f"(d[2]), "+f"(d[3])
                 : "r"(a[0]), "r"(a[1]), "r"(a[2]), "r"(a[3]), "r"(b0), "r"(b1));
}
__device__ __forceinline__ void ldsm4(uint32_t* r, uint32_t addr) {
    asm volatile("ldmatrix.sync.aligned.m8n8.x4.shared.b16 {%0,%1,%2,%3}, [%4];"
                 : "=r"(r[0]), "=r"(r[1]), "=r"(r[2]), "=r"(r[3]) : "r"(addr));
}
__device__ __forceinline__ void cpa16(uint32_t saddr, const void* gaddr, int bytes) {
    asm volatile("cp.async.cg.shared.global [%0], [%1], 16, %2;"
                 :: "r"(saddr), "l"(gaddr), "r"(bytes));
}

extern __shared__ char dynsmem[];

__global__ void __launch_bounds__(256, 2)
gemm_bf16(const float* __restrict__ b0a, const float* __restrict__ b0b,
          const int* __restrict__ ei) {
    int t = threadIdx.x;

    if (blockIdx.y >= MTILES) {
        int idx = (blockIdx.y - MTILES) * 4 + blockIdx.x;
        int e = idx * 256 + t;
        if (e < EE) atomicAdd(&d_rowptr[ei[EE + e] + 1], 1);
        return;
    }

    int mat = blockIdx.x >> 1;
    int n0 = (blockIdx.x & 1) * 128;
    int m0 = blockIdx.y * 128;
    const __nv_bfloat16* Bh = d_w_hi + mat * 65536;
    const __nv_bfloat16* Bl = d_w_lo + mat * 65536;

    int lrow = t >> 1, seg = t & 1;
    int gm = m0 + lrow;
    bool aok = gm < NN;
    int gmc = aok ? gm : 0;
    int abytes = aok ? 16 : 0;

    const char* gAh = (const char*)(d_a_hi + (size_t)gmc * 256) + seg * 16;
    const char* gAl = (const char*)(d_a_lo + (size_t)gmc * 256) + seg * 16;
    const char* gBh = (const char*)(Bh + (size_t)(n0 + lrow) * 256) + seg * 16;
    const char* gBl = (const char*)(Bl + (size_t)(n0 + lrow) * 256) + seg * 16;

    uint32_t smem0 = (uint32_t)__cvta_generic_to_shared(dynsmem);
    uint32_t rowoff = (uint32_t)(lrow * 48 + seg * 16);

    auto issue = [&](int slab, int buf) {
        uint32_t base = smem0 + buf * STG + rowoff;
        int go = slab * 32;
        cpa16(base,             gAh + go, abytes);
        cpa16(base + PLANE,     gAl + go, abytes);
        cpa16(base + 2 * PLANE, gBh + go, 16);
        cpa16(base + 3 * PLANE, gBl + go, 16);
        asm volatile("cp.async.commit_group;");
    };

    issue(0, 0);
    issue(1, 1);
    issue(2, 2);

    int wid = t >> 5, lane = t & 31;
    int wm0 = (wid & 1) * 64, wn0 = (wid >> 1) * 32;
    float acc[4][4][4] = {};

    int a_r = (lane & 15);
    int a_c = (lane >> 4) << 3;
    int b_r = (lane & 7) + ((lane & 16) ? 8 : 0);
    int b_c = (lane & 8) ? 8 : 0;

    for (int s = 0; s < 16; s++) {
        asm volatile("cp.async.wait_group 2;");
        __syncthreads();
        if (s + 3 < 16) issue(s + 3, (s + 3) & 3);
        else            asm volatile("cp.async.commit_group;");

        uint32_t sAu = smem0 + (s & 3) * STG;
        uint32_t sBu = sAu + 2 * PLANE;
        uint32_t bh[2][4], bl[2][4];
        #pragma unroll
        for (int jp = 0; jp < 2; jp++) {
            uint32_t addr = sBu + (uint32_t)(((wn0 + jp * 16 + b_r) * SLDA + b_c) * 2);
            ldsm4(bh[jp], addr);
            ldsm4(bl[jp], addr + PLANE);
        }
        #pragma unroll
        for (int i = 0; i < 4; i++) {
            uint32_t ah[4], al[4];
            uint32_t addr = sAu + (uint32_t)(((wm0 + i * 16 + a_r) * SLDA + a_c) * 2);
            ldsm4(ah, addr);
            ldsm4(al, addr + PLANE);
            #pragma unroll
            for (int j = 0; j < 4; j++) {
                int jp = j >> 1, o = (j & 1) * 2;
                mma16816(acc[i][j], ah, bh[jp][o], bh[jp][o + 1]);
                mma16816(acc[i][j], ah, bl[jp][o], bl[jp][o + 1]);
                mma16816(acc[i][j], al, bh[jp][o], bh[jp][o + 1]);
            }
        }
    }

    int g = lane >> 2, tq = lane & 3;
    if (!mat) {
        float* C = (float*)d_y1;
        #pragma unroll
        for (int j = 0; j < 4; j++) {
            int gcol = n0 + wn0 + j * 8 + tq * 2;
            float bx = b0a[gcol] + b0b[gcol];
            float by = b0a[gcol + 1] + b0b[gcol + 1];
            #pragma unroll
            for (int i = 0; i < 4; i++) {
                int r0 = m0 + wm0 + i * 16 + g;
                if (r0 < NN)
                    *(float2*)&C[(size_t)r0 * 256 + gcol] =
                        make_float2(acc[i][j][0] + bx, acc[i][j][1] + by);
                int r1 = r0 + 8;
                if (r1 < NN)
                    *(float2*)&C[(size_t)r1 * 256 + gcol] =
                        make_float2(acc[i][j][2] + bx, acc[i][j][3] + by);
            }
        }
    } else {
        __half* C = (__half*)d_h1h;
        #pragma unroll
        for (int j = 0; j < 4; j++) {
            int gcol = n0 + wn0 + j * 8 + tq * 2;
            #pragma unroll
            for (int i = 0; i < 4; i++) {
                int r0 = m0 + wm0 + i * 16 + g;
                if (r0 < NN)
                    *(__half2*)&C[(size_t)r0 * 256 + gcol] =
                        __floats2half2_rn(acc[i][j][0], acc[i][j][1]);
                int r1 = r0 + 8;
                if (r1 < NN)
                    *(__half2*)&C[(size_t)r1 * 256 + gcol] =
                        __floats2half2_rn(acc[i][j][2], acc[i][j][3]);
            }
        }
    }
}

// ---------------- layer-1 GAT + ReLU + fused BN3 stats (NO smem atomics) ----------------
// warp/dst; grid is exactly 50000 warps so every warp is active.
// Per-warp private smem slabs -> conflict-free stores; tree-free column reduce;
// ONE global atomicAdd per channel per block.
__global__ void gat1_warp() {
    __shared__ float s_sum[8][FDIM];
    __shared__ float s_sq[8][FDIM];
    int t = threadIdx.x;
    int wid = t >> 5;
    int lane = t & 31;
    int coff = lane * 8;

    int d = (blockIdx.x * blockDim.x + t) >> 5;
    int b = d_rowptr[d], e = d_rowptr[d + 1];
    float4* yp = (float4*)&d_y1[(size_t)d * 256 + coff];
    float4 o0 = yp[0], o1 = yp[1];

    if (b != e) {
        float4 ald = d_ald1[d];
        int h = lane >> 3;
        float4 acc0 = make_float4(0.f, 0.f, 0.f, 0.f);
        float4 acc1 = make_float4(0.f, 0.f, 0.f, 0.f);
        float den = 0.f;
        const __half* __restrict__ hp = (const __half*)d_h1h;
        for (int c0 = b; c0 < e; c0 += 32) {
            int cnt = min(32, e - c0);
            int src = 0;
            float4 ex = make_float4(0.f, 0.f, 0.f, 0.f);
            if (lane < cnt) {
                src = d_csr_src[c0 + lane];
                float4 a = d_als1[src];
                ex.x = __expf(lrelu(a.x + ald.x));
                ex.y = __expf(lrelu(a.y + ald.y));
                ex.z = __expf(lrelu(a.z + ald.z));
                ex.w = __expf(lrelu(a.w + ald.w));
            }
            #pragma unroll 4
            for (int j = 0; j < cnt; j++) {
                int   sj = __shfl_sync(0xffffffffu, src,  j);
                float e0 = __shfl_sync(0xffffffffu, ex.x, j);
                float e1 = __shfl_sync(0xffffffffu, ex.y, j);
                float e2 = __shfl_sync(0xffffffffu, ex.z, j);
                float e3 = __shfl_sync(0xffffffffu, ex.w, j);
                float w = (h == 0) ? e0 : (h == 1) ? e1 : (h == 2) ? e2 : e3;
                den += w;
                uint4 raw = *(const uint4*)&hp[(size_t)sj * 256 + coff];
                float2 f0 = __half22float2(*(__half2*)&raw.x);
                float2 f1 = __half22float2(*(__half2*)&raw.y);
                float2 f2 = __half22float2(*(__half2*)&raw.z);
                float2 f3 = __half22float2(*(__half2*)&raw.w);
                acc0.x += w * f0.x; acc0.y += w * f0.y;
                acc0.z += w * f1.x; acc0.w += w * f1.y;
                acc1.x += w * f2.x; acc1.y += w * f2.y;
                acc1.z += w * f3.x; acc1.w += w * f3.y;
            }
        }
        float r = 1.f / (den + 1e-16f);
        o0.x += acc0.x * r; o0.y += acc0.y * r; o0.z += acc0.z * r; o0.w += acc0.w * r;
        o1.x += acc1.x * r; o1.y += acc1.y * r; o1.z += acc1.z * r; o1.w += acc1.w * r;
    }
    // ReLU (isolated nodes too — their GAT message is 0)
    o0.x = fmaxf(o0.x, 0.f); o0.y = fmaxf(o0.y, 0.f);
    o0.z = fmaxf(o0.z, 0.f); o0.w = fmaxf(o0.w, 0.f);
    o1.x = fmaxf(o1.x, 0.f); o1.y = fmaxf(o1.y, 0.f);
    o1.z = fmaxf(o1.z, 0.f); o1.w = fmaxf(o1.w, 0.f);
    yp[0] = o0; yp[1] = o1;

    // BN3 stats: conflict-free per-warp slabs
    *(float4*)&s_sum[wid][coff]     = o0;
    *(float4*)&s_sum[wid][coff + 4] = o1;
    *(float4*)&s_sq[wid][coff]      = make_float4(o0.x*o0.x, o0.y*o0.y, o0.z*o0.z, o0.w*o0.w);
    *(float4*)&s_sq[wid][coff + 4]  = make_float4(o1.x*o1.x, o1.y*o1.y, o1.z*o1.z, o1.w*o1.w);
    __syncthreads();
    float s = 0.f, q = 0.f;
    #pragma unroll
    for (int w = 0; w < 8; w++) {
        s += s_sum[w][t];
        q += s_sq[w][t];
    }
    atomicAdd(&d_bnsum2[t], s);
    atomicAdd(&d_bnsq2[t], q);
}

// ---------------- layer 2: BN (x1 already relu'd) + linear3 + GAT2 features/logits ----------------
__global__ void layer2_row(const float* __restrict__ lin3W, const float* __restrict__ lin3b,
                           const float* __restrict__ con3W, const float* __restrict__ asrc,
                           const float* __restrict__ adst, const float* __restrict__ con3b,
                           float* __restrict__ out) {
    int warp = (blockIdx.x * blockDim.x + threadIdx.x) >> 5;
    int lane = threadIdx.x & 31;
    if (warp >= NN) return;
    const float* row = (const float*)d_y1 + (size_t)warp * 256;
    float y0 = 0.f, y1v = 0.f, h0 = 0.f, h1v = 0.f;
    #pragma unroll
    for (int q = 0; q < 8; q++) {
        int c = lane + q * 32;
        float v = row[c] * d_scale[c] + d_shift[c];
        y0  += v * lin3W[c * 2];
        y1v += v * lin3W[c * 2 + 1];
        h0  += v * con3W[c * 2];
        h1v += v * con3W[c * 2 + 1];
    }
    #pragma unroll
    for (int off = 16; off > 0; off >>= 1) {
        y0  += __shfl_xor_sync(0xffffffff, y0,  off);
        y1v += __shfl_xor_sync(0xffffffff, y1v, off);
        h0  += __shfl_xor_sync(0xffffffff, h0,  off);
        h1v += __shfl_xor_sync(0xffffffff, h1v, off);
    }
    if (lane == 0) {
        out[warp * 2]     = y0  + lin3b[0] + con3b[0];
        out[warp * 2 + 1] = y1v + lin3b[1] + con3b[1];
        d_p3[warp] = make_float4(h0 * asrc[0] + h1v * asrc[1],
                                 h0, h1v,
                                 h0 * adst[0] + h1v * adst[1]);
    }
}

// ---------------- layer-2 GAT + final relu (warp/dst, single LDG.128 per edge) ----------------
__global__ void gat_l2(float* __restrict__ out) {
    int d = (blockIdx.x * blockDim.x + threadIdx.x) >> 5;
    int lane = threadIdx.x & 31;
    if (d >= NN) return;
    int b = d_rowptr[d], e = d_rowptr[d + 1];
    float ald = d_p3[d].w;
    float den = 0.f, m0 = 0.f, m1 = 0.f;
    for (int j = b + lane; j < e; j += 32) {
        int src = d_csr_src[j];
        float4 p = d_p3[src];
        float ex = __expf(lrelu(p.x + ald));
        den += ex; m0 += ex * p.y; m1 += ex * p.z;
    }
    #pragma unroll
    for (int off = 16; off > 0; off >>= 1) {
        den += __shfl_xor_sync(0xffffffff, den, off);
        m0  += __shfl_xor_sync(0xffffffff, m0,  off);
        m1  += __shfl_xor_sync(0xffffffff, m1,  off);
    }
    if (lane == 0) {
        float r = 1.f / (den + 1e-16f);
        out[d * 2]     = fmaxf(out[d * 2]     + m0 * r, 0.f);
        out[d * 2 + 1] = fmaxf(out[d * 2 + 1] + m1 * r, 0.f);
    }
}

// ---------------- launch ----------------
extern "C" void kernel_launch(void* const* d_in, const int* in_sizes, int n_in,
                              void* d_out, int out_size) {
    const float* x         = (const float*)d_in[0];
    const int*   ei        = (const int*)d_in[1];
    const float* bn1_g     = (const float*)d_in[2];
    const float* bn1_b     = (const float*)d_in[3];
    const float* lin1_W    = (const float*)d_in[4];
    const float* lin1_b    = (const float*)d_in[5];
    const float* con1_W    = (const float*)d_in[6];
    const float* con1_asrc = (const float*)d_in[7];
    const float* con1_adst = (const float*)d_in[8];
    const float* con1_b    = (const float*)d_in[9];
    const float* bn3_g     = (const float*)d_in[10];
    const float* bn3_b     = (const float*)d_in[11];
    const float* lin3_W    = (const float*)d_in[12];
    const float* lin3_b    = (const float*)d_in[13];
    const float* con3_W    = (const float*)d_in[14];
    const float* con3_asrc = (const float*)d_in[15];
    const float* con3_adst = (const float*)d_in[16];
    const float* con3_b    = (const float*)d_in[17];
    float* out = (float*)d_out;

    const int NCHUNK = (NN + 1 + 1023) / 1024;   // 49

    cudaFuncSetAttribute(gemm_bf16, cudaFuncAttributeMaxDynamicSharedMemorySize, GSMEM);

    // 1-3: BN1 stats/finalize, fused prep (bnconv + wtconv + rowptr/BN3-acc zero)
    bn_stats<<<BNPART, 256>>>(x);
    bn_finalize<<<1, 256>>>(bn1_g, bn1_b);
    prep_k<<<PREP_A + PREP_W + PREP_Z, 256>>>(x, lin1_W, con1_W);

    // 4 (ncu-profiled slot): dual GEMM + histogram tail blocks
    gemm_bf16<<<dim3(4, MTILES + HISTROWS), 256, GSMEM>>>(lin1_b, con1_b, ei);

    // 5-6: CSR scan, cursor init fused
    scan1_k<<<NCHUNK, 1024>>>();
    scan3_k<<<NCHUNK - 1, 1024>>>();

    // 7: fused scatter + layer-1 logit contributions
    scatter_al_k<<<SCAT_B + AL_B, 256>>>(ei, con1_asrc, con1_adst);

    // 8: GAT1 softmax+aggregate + ReLU + fused BN3 stats (atomic-free hot path)
    gat1_warp<<<(NN + 7) / 8, 256>>>();

    // 9: BN3 finalize (reads accumulators)
    bn_finalize2<<<1, 256>>>(bn3_g, bn3_b);

    // 10-11: layer 2
    layer2_row<<<(NN + 7) / 8, 256>>>(lin3_W, lin3_b, con3_W, con3_asrc, con3_adst, con3_b, out);
    gat_l2<<<(NN + 7) / 8, 256>>>(out);
}